// round 2
// baseline (speedup 1.0000x reference)
#include <cuda_runtime.h>
#include <cstdint>

#define ST 136    // main-kernel smem row stride (floats): 8 mod 32 -> conflict-free half-warp .64
#define STX 132   // xs-kernel stride (unchanged, proven)

// Scratch for x_s = x @ Wx^T + bx
__device__ float g_xs[65536 * 128];

__device__ __forceinline__ uint32_t f2tf32(float f) {
    uint32_t r;
    asm volatile("cvt.rna.tf32.f32 %0, %1;" : "=r"(r) : "f"(f));
    return r;
}

__device__ __forceinline__ void mma_tf32(float c[4], const uint32_t a[4], const uint32_t b[2]) {
    asm volatile(
        "mma.sync.aligned.m16n8k8.row.col.f32.tf32.tf32.f32 "
        "{%0,%1,%2,%3}, {%4,%5,%6,%7}, {%8,%9}, {%0,%1,%2,%3};"
        : "+f"(c[0]), "+f"(c[1]), "+f"(c[2]), "+f"(c[3])
        : "r"(a[0]), "r"(a[1]), "r"(a[2]), "r"(a[3]), "r"(b[0]), "r"(b[1]));
}

__device__ __forceinline__ void cpa16(uint32_t dst, const void* src) {
    asm volatile("cp.async.cg.shared.global [%0], [%1], 16;" :: "r"(dst), "l"(src));
}

// ---------------------------------------------------------------------------
// Kernel 1: x_s[n,d] = x @ Wx^T + bx  -> g_xs   (unchanged from round 1)
// ---------------------------------------------------------------------------
__global__ __launch_bounds__(256) void xs_kernel(
    const float* __restrict__ x, const float* __restrict__ Wx,
    const float* __restrict__ bx, int N)
{
    extern __shared__ float smem[];
    float* sW  = smem;
    float* sA  = sW + 128 * STX;
    float* sbx = sA + 128 * STX;

    const int tid = threadIdx.x;
    const int tileBase = blockIdx.x * 128;

    for (int i = tid; i < 128 * 128; i += 256) {
        int d = i >> 7, e = i & 127;
        ((uint32_t*)sW)[d * STX + e] = f2tf32(Wx[i]);
    }
    for (int i = tid; i < 128 * 128; i += 256) {
        int r = i >> 7, e = i & 127;
        int node = tileBase + r;
        float v = (node < N) ? x[node * 128 + e] : 0.f;
        ((uint32_t*)sA)[r * STX + e] = f2tf32(v);
    }
    if (tid < 128) sbx[tid] = bx[tid];
    __syncthreads();

    const int w = tid >> 5, lane = tid & 31;
    const int lg = lane >> 2, lc = lane & 3;
    const int wm = w >> 1, wn = w & 1;

    float acc[2][8][4];
#pragma unroll
    for (int mi = 0; mi < 2; mi++)
#pragma unroll
        for (int ni = 0; ni < 8; ni++)
#pragma unroll
            for (int j = 0; j < 4; j++) acc[mi][ni][j] = 0.f;

    const uint32_t* uA = (const uint32_t*)sA;
    const uint32_t* uW = (const uint32_t*)sW;

#pragma unroll 4
    for (int ks = 0; ks < 16; ks++) {
        const int e0 = ks * 8;
        uint32_t afr[2][4];
#pragma unroll
        for (int mi = 0; mi < 2; mi++) {
            int r = wm * 32 + mi * 16 + lg;
            afr[mi][0] = uA[r * STX + e0 + lc];
            afr[mi][1] = uA[(r + 8) * STX + e0 + lc];
            afr[mi][2] = uA[r * STX + e0 + 4 + lc];
            afr[mi][3] = uA[(r + 8) * STX + e0 + 4 + lc];
        }
#pragma unroll
        for (int ni = 0; ni < 8; ni++) {
            int c0 = wn * 64 + ni * 8;
            uint32_t bfr[2];
            bfr[0] = uW[(c0 + lg) * STX + e0 + lc];
            bfr[1] = uW[(c0 + lg) * STX + e0 + 4 + lc];
            mma_tf32(acc[0][ni], afr[0], bfr);
            mma_tf32(acc[1][ni], afr[1], bfr);
        }
    }

#pragma unroll
    for (int mi = 0; mi < 2; mi++) {
#pragma unroll
        for (int rh = 0; rh < 2; rh++) {
            int r = wm * 32 + mi * 16 + rh * 8 + lg;
            int node = tileBase + r;
            if (node < N) {
#pragma unroll
                for (int ni = 0; ni < 8; ni++) {
#pragma unroll
                    for (int cc = 0; cc < 2; cc++) {
                        int d = wn * 64 + ni * 8 + 2 * lc + cc;
                        g_xs[node * 128 + d] = acc[mi][ni][rh * 2 + cc] + sbx[d];
                    }
                }
            }
        }
    }
}

// ---------------------------------------------------------------------------
// Main kernel: 512 threads, 16 warps = 2(wm:M32) x 4(wn:N32) x 2(wk:K64).
// Wn B-fragments in registers (64 regs), A via float2 LDS with k-slot
// pair remap, cp.async double-buffered tile prefetch, split-K smem reduce.
// ---------------------------------------------------------------------------
__global__ __launch_bounds__(512, 1) void gnn_main_kernel(
    const float* __restrict__ x_nb, const float* __restrict__ weight,
    const float* __restrict__ Wn, const float* __restrict__ bn,
    const float* __restrict__ Ww, const float* __restrict__ bw,
    const float* __restrict__ Wl,
    float* __restrict__ out, int N, int numTiles)
{
    extern __shared__ float smem[];
    float* sA    = smem;                 // 2 x 64 x ST  (x_nb tile, fp32, double-buffered)
    float* sRed  = sA + 2 * 64 * ST;     // 64 x ST      (split-K partials)
    float* sxs   = sRed + 64 * ST;       // 2 x 256
    float* swt   = sxs + 512;            // 2 x 64
    float* spart = swt + 128;            // 64 x 4
    float* sattn = spart + 256;          // 64
    float* sOutP = sattn + 64;           // 256
    float* sWw   = sOutP + 256;          // 128
    float* scb   = sWw + 128;            // 128
    float* sWl   = scb + 128;            // 128

    const int tid  = threadIdx.x;
    const int w    = tid >> 5, lane = tid & 31;
    const int lg   = lane >> 2, lc = lane & 3;
    const int wk   = w >> 3;          // 0/1 : K-half
    const int wm   = (w >> 2) & 1;    // 0/1 : M32 block
    const int wn   = w & 3;           // 0..3: N32 block

    const uint32_t smemBase = (uint32_t)__cvta_generic_to_shared(smem);
    const uint32_t aOff  = 0;
    const uint32_t xsOff = (uint32_t)((2 * 64 * ST + 64 * ST) * 4);
    const uint32_t wtOff = xsOff + 512 * 4;

    // One-time constants
    if (tid < 128) {
        sWw[tid] = Ww[tid];
        scb[tid] = bn[tid] + bw[tid];
        sWl[tid] = Wl[tid];
    }

    // One-time Wn B-fragment preload into registers.
    // Physical k pair (e+2lc, e+2lc+1) -> mma k-slots (lc, lc+4). Valid because the
    // k-sum is permutation invariant and A uses the same remap.
    uint32_t breg[8][4][2];
    {
        const int cbase = wn * 32 + lg;
#pragma unroll
        for (int ks = 0; ks < 8; ks++)
#pragma unroll
            for (int ni = 0; ni < 4; ni++) {
                float2 v = *(const float2*)(Wn + (size_t)(cbase + ni * 8) * 128
                                            + wk * 64 + ks * 8 + 2 * lc);
                breg[ks][ni][0] = f2tf32(v.x);
                breg[ks][ni][1] = f2tf32(v.y);
            }
    }

    const int grid = gridDim.x;
    int t = blockIdx.x;
    int pb = 0;

    // Prefetch tile tt into buffer pbuf
    auto prefetch = [&](int tt, int pbuf) {
        if (tt < numTiles) {
            const long qbase = (long)tt * 2048;
            const long qmax  = (long)N * 1024 - 1;
            const uint32_t abase = smemBase + aOff + (uint32_t)(pbuf * 64 * ST * 4);
#pragma unroll
            for (int i = 0; i < 4; i++) {
                const int qi = tid + i * 512;
                long q = qbase + qi; if (q > qmax) q = qmax;
                const int r = qi >> 5, c = qi & 31;
                cpa16(abase + (uint32_t)((r * ST + c * 4) * 4), (const float4*)x_nb + q);
            }
            if (tid < 64) {
                cpa16(smemBase + xsOff + (uint32_t)(pbuf * 256 * 4) + tid * 16,
                      (const float4*)g_xs + (long)tt * 64 + tid);
            } else if (tid < 80) {
                const int j = tid - 64;
                long wq = (long)tt * 16 + j;
                const long wmax = (long)N * 8 - 1; if (wq > wmax) wq = wmax;
                cpa16(smemBase + wtOff + (uint32_t)(pbuf * 64 * 4) + j * 16,
                      (const float4*)weight + wq);
            }
        }
        asm volatile("cp.async.commit_group;");
    };

    prefetch(t, 0);

    for (; t < numTiles; t += grid, pb ^= 1) {
        asm volatile("cp.async.wait_group 0;");
        __syncthreads();                       // buf[pb] ready, previous tile fully consumed
        prefetch(t + grid, pb ^ 1);

        const float* A = sA + pb * 64 * ST;

        // ---- GEMM: n_s partial (this warp: M32 x N32 x K64) ----
        float acc[2][4][4];
#pragma unroll
        for (int mi = 0; mi < 2; mi++)
#pragma unroll
            for (int ni = 0; ni < 4; ni++)
#pragma unroll
                for (int j = 0; j < 4; j++) acc[mi][ni][j] = 0.f;

#pragma unroll
        for (int ks = 0; ks < 8; ks++) {
            const int e = wk * 64 + ks * 8 + 2 * lc;
            uint32_t a[2][4];
#pragma unroll
            for (int mi = 0; mi < 2; mi++) {
                const int r = wm * 32 + mi * 16 + lg;
                float2 x0 = *(const float2*)(A + r * ST + e);
                float2 x1 = *(const float2*)(A + (r + 8) * ST + e);
                a[mi][0] = f2tf32(x0.x);
                a[mi][2] = f2tf32(x0.y);
                a[mi][1] = f2tf32(x1.x);
                a[mi][3] = f2tf32(x1.y);
            }
#pragma unroll
            for (int ni = 0; ni < 4; ni++) {
                mma_tf32(acc[0][ni], a[0], breg[ks][ni]);
                mma_tf32(acc[1][ni], a[1], breg[ks][ni]);
            }
        }

        // ---- split-K: wk=1 stores partials ----
        if (wk == 1) {
#pragma unroll
            for (int mi = 0; mi < 2; mi++)
#pragma unroll
                for (int ni = 0; ni < 4; ni++) {
                    const int r = wm * 32 + mi * 16 + lg;
                    const int c = wn * 32 + ni * 8 + 2 * lc;
                    *(float2*)(sRed + r * ST + c) =
                        make_float2(acc[mi][ni][0], acc[mi][ni][1]);
                    *(float2*)(sRed + (r + 8) * ST + c) =
                        make_float2(acc[mi][ni][2], acc[mi][ni][3]);
                }
        }
        __syncthreads();

        // ---- wk=0: reduce, scores (h = n_s + x_s + bn + bw + weight*Ww; leaky; .Wl) ----
        if (wk == 0) {
#pragma unroll
            for (int mi = 0; mi < 2; mi++)
#pragma unroll
                for (int ni = 0; ni < 4; ni++) {
                    const int r = wm * 32 + mi * 16 + lg;
                    const int c = wn * 32 + ni * 8 + 2 * lc;
                    float2 p0 = *(const float2*)(sRed + r * ST + c);
                    float2 p1 = *(const float2*)(sRed + (r + 8) * ST + c);
                    acc[mi][ni][0] += p0.x; acc[mi][ni][1] += p0.y;
                    acc[mi][ni][2] += p1.x; acc[mi][ni][3] += p1.y;
                }
            const float* xsb = sxs + pb * 256;
            const float* wtb = swt + pb * 64;
#pragma unroll
            for (int mi = 0; mi < 2; mi++)
#pragma unroll
                for (int rh = 0; rh < 2; rh++) {
                    const int r = wm * 32 + mi * 16 + rh * 8 + lg;
                    const int node = r >> 5, k = r & 31;
                    const float wgt = wtb[node * 32 + k];
                    float p = 0.f;
#pragma unroll
                    for (int ni = 0; ni < 4; ni++)
#pragma unroll
                        for (int cc = 0; cc < 2; cc++) {
                            const int d = wn * 32 + ni * 8 + 2 * lc + cc;
                            float h = acc[mi][ni][rh * 2 + cc] + xsb[node * 128 + d]
                                    + scb[d] + wgt * sWw[d];
                            h = (h >= 0.f) ? h : 0.1f * h;
                            p += sWl[d] * h;
                        }
                    p += __shfl_xor_sync(0xffffffffu, p, 1);
                    p += __shfl_xor_sync(0xffffffffu, p, 2);
                    if (lc == 0) spart[r * 4 + wn] = p;
                }
        }
        __syncthreads();

        // ---- softmax over K=32 (bl dropped: softmax-invariant) ----
        if (tid < 64) {
            const int r = tid;
            float s = spart[r * 4] + spart[r * 4 + 1] + spart[r * 4 + 2] + spart[r * 4 + 3];
            float m = s;
#pragma unroll
            for (int o = 16; o; o >>= 1) m = fmaxf(m, __shfl_xor_sync(0xffffffffu, m, o));
            float e = expf(s - m);
            float su = e;
#pragma unroll
            for (int o = 16; o; o >>= 1) su += __shfl_xor_sync(0xffffffffu, su, o);
            sattn[r] = e / su;
        }
        __syncthreads();

        // ---- output: out[n,d] = sum_k attn * x_nb (k split over 2 thread halves) ----
        {
            const int node = tid >> 8, half = (tid >> 7) & 1, d = tid & 127;
            float s = 0.f;
#pragma unroll
            for (int kk = 0; kk < 16; kk++) {
                const int k = half * 16 + kk;
                s += sattn[node * 32 + k] * A[(node * 32 + k) * ST + d];
            }
            if (half == 1) sOutP[node * 128 + d] = s;
            __syncthreads();
            if (half == 0) {
                s += sOutP[node * 128 + d];
                const int gn = t * 2 + node;
                if (gn < N) out[gn * 128 + d] = s;
            }
        }
    }
}

// ---------------------------------------------------------------------------
extern "C" void kernel_launch(void* const* d_in, const int* in_sizes, int n_in,
                              void* d_out, int out_size)
{
    const float* x      = (const float*)d_in[0];
    const float* x_nb   = (const float*)d_in[1];
    const float* weight = (const float*)d_in[2];
    const float* Wx     = (const float*)d_in[3];
    const float* bx     = (const float*)d_in[4];
    const float* Wn     = (const float*)d_in[5];
    const float* bn     = (const float*)d_in[6];
    const float* Ww     = (const float*)d_in[7];
    const float* bw     = (const float*)d_in[8];
    const float* Wl     = (const float*)d_in[9];
    // d_in[10] = bl: softmax-invariant, unused.
    float* out = (float*)d_out;

    const int N = in_sizes[0] / 128;

    const size_t smem1 = (size_t)(2 * 128 * STX + 128) * sizeof(float);
    const size_t smem2 = (size_t)(2 * 64 * ST + 64 * ST + 512 + 128 + 256 + 64
                                  + 256 + 128 + 128 + 128) * sizeof(float);
    cudaFuncSetAttribute(xs_kernel, cudaFuncAttributeMaxDynamicSharedMemorySize, (int)smem1);
    cudaFuncSetAttribute(gnn_main_kernel, cudaFuncAttributeMaxDynamicSharedMemorySize, (int)smem2);

    int nSM = 148;
    cudaDeviceGetAttribute(&nSM, cudaDevAttrMultiProcessorCount, 0);

    const int blocks1 = (N + 127) / 128;
    xs_kernel<<<blocks1, 256, smem1>>>(x, Wx, bx, N);

    const int numTiles = (N + 1) / 2;
    int grid = nSM;
    if (grid > numTiles) grid = numTiles;
    gnn_main_kernel<<<grid, 512, smem2>>>(x_nb, weight, Wn, bn, Ww, bw, Wl, out, N, numTiles);
}

// round 5
// speedup vs baseline: 1.5285x; 1.5285x over previous
#include <cuda_runtime.h>
#include <cuda_bf16.h>
#include <cstdint>

#define STX 132      // xs-kernel smem stride (proven)
#define ATS 144      // main-kernel A stride in bf16 units (288B: conflict-free half-warp LDS.64)

// Scratch for x_s = x @ Wx^T + bx
__device__ float g_xs[65536 * 128];

__device__ __forceinline__ uint32_t f2tf32(float f) {
    uint32_t r; asm volatile("cvt.rna.tf32.f32 %0, %1;" : "=r"(r) : "f"(f)); return r;
}
__device__ __forceinline__ void mma_tf32_frag(float c[4], const uint32_t a[4], const uint32_t b[2]) {
    asm volatile(
        "mma.sync.aligned.m16n8k8.row.col.f32.tf32.tf32.f32 "
        "{%0,%1,%2,%3}, {%4,%5,%6,%7}, {%8,%9}, {%0,%1,%2,%3};"
        : "+f"(c[0]), "+f"(c[1]), "+f"(c[2]), "+f"(c[3])
        : "r"(a[0]), "r"(a[1]), "r"(a[2]), "r"(a[3]), "r"(b[0]), "r"(b[1]));
}
__device__ __forceinline__ void mma_bf16(float c[4], const uint32_t a[4], const uint32_t b[2]) {
    asm volatile(
        "mma.sync.aligned.m16n8k16.row.col.f32.bf16.bf16.f32 "
        "{%0,%1,%2,%3}, {%4,%5,%6,%7}, {%8,%9}, {%0,%1,%2,%3};"
        : "+f"(c[0]), "+f"(c[1]), "+f"(c[2]), "+f"(c[3])
        : "r"(a[0]), "r"(a[1]), "r"(a[2]), "r"(a[3]), "r"(b[0]), "r"(b[1]));
}
__device__ __forceinline__ uint32_t pack_bf16(float lo, float hi) {
    __nv_bfloat162 v = __floats2bfloat162_rn(lo, hi);   // .x = lo (low 16 bits)
    return *reinterpret_cast<uint32_t*>(&v);
}

// ---------------------------------------------------------------------------
// Kernel 1: x_s = x @ Wx^T + bx  (tf32, unchanged — proven)
// ---------------------------------------------------------------------------
__global__ __launch_bounds__(256) void xs_kernel(
    const float* __restrict__ x, const float* __restrict__ Wx,
    const float* __restrict__ bx, int N)
{
    extern __shared__ float smem[];
    float* sW  = smem;
    float* sA  = sW + 128 * STX;
    float* sbx = sA + 128 * STX;
    const int tid = threadIdx.x;
    const int tileBase = blockIdx.x * 128;

    for (int i = tid; i < 128 * 128; i += 256) {
        int d = i >> 7, e = i & 127;
        ((uint32_t*)sW)[d * STX + e] = f2tf32(Wx[i]);
    }
    for (int i = tid; i < 128 * 128; i += 256) {
        int r = i >> 7, e = i & 127;
        int node = tileBase + r;
        float v = (node < N) ? x[node * 128 + e] : 0.f;
        ((uint32_t*)sA)[r * STX + e] = f2tf32(v);
    }
    if (tid < 128) sbx[tid] = bx[tid];
    __syncthreads();

    const int w = tid >> 5, lane = tid & 31;
    const int lg = lane >> 2, lc = lane & 3;
    const int wm = w >> 1, wn = w & 1;

    float acc[2][8][4];
#pragma unroll
    for (int mi = 0; mi < 2; mi++)
#pragma unroll
        for (int ni = 0; ni < 8; ni++)
#pragma unroll
            for (int j = 0; j < 4; j++) acc[mi][ni][j] = 0.f;

    const uint32_t* uA = (const uint32_t*)sA;
    const uint32_t* uW = (const uint32_t*)sW;
#pragma unroll 4
    for (int ks = 0; ks < 16; ks++) {
        const int e0 = ks * 8;
        uint32_t afr[2][4];
#pragma unroll
        for (int mi = 0; mi < 2; mi++) {
            int r = wm * 32 + mi * 16 + lg;
            afr[mi][0] = uA[r * STX + e0 + lc];
            afr[mi][1] = uA[(r + 8) * STX + e0 + lc];
            afr[mi][2] = uA[r * STX + e0 + 4 + lc];
            afr[mi][3] = uA[(r + 8) * STX + e0 + 4 + lc];
        }
#pragma unroll
        for (int ni = 0; ni < 8; ni++) {
            int c0 = wn * 64 + ni * 8;
            uint32_t bfr[2];
            bfr[0] = uW[(c0 + lg) * STX + e0 + lc];
            bfr[1] = uW[(c0 + lg) * STX + e0 + 4 + lc];
            mma_tf32_frag(acc[0][ni], afr[0], bfr);
            mma_tf32_frag(acc[1][ni], afr[1], bfr);
        }
    }
#pragma unroll
    for (int mi = 0; mi < 2; mi++)
#pragma unroll
        for (int rh = 0; rh < 2; rh++) {
            int r = wm * 32 + mi * 16 + rh * 8 + lg;
            int node = tileBase + r;
            if (node < N) {
#pragma unroll
                for (int ni = 0; ni < 8; ni++)
#pragma unroll
                    for (int cc = 0; cc < 2; cc++) {
                        int d = wn * 64 + ni * 8 + 2 * lc + cc;
                        g_xs[node * 128 + d] = acc[mi][ni][rh * 2 + cc] + sbx[d];
                    }
            }
        }
}

// ---------------------------------------------------------------------------
// Main kernel: persistent, 256 threads, 2 CTAs/SM.
// 8 warps = 2(wm:M32) x 4(wn:N32), full K=128 per warp, bf16 m16n8k16.
// Wn B-fragments in registers (64 regs, preconverted bf16). A tile in smem
// as bf16 (converted at STS). Physical-k pair remap -> every fragment is
// one LDS.64; ATS=144 bf16 stride -> conflict-free per half-warp phase.
// ---------------------------------------------------------------------------
__global__ __launch_bounds__(256, 2) void gnn_main_kernel(
    const float* __restrict__ x_nb, const float* __restrict__ weight,
    const float* __restrict__ Wn, const float* __restrict__ bn,
    const float* __restrict__ Ww, const float* __restrict__ bw,
    const float* __restrict__ Wl,
    float* __restrict__ out, int N, int numTiles)
{
    __shared__ __align__(16) __nv_bfloat16 sA[64 * ATS];   // 18432 B
    __shared__ float sxs[256];     // 2 nodes x 128
    __shared__ float swt[64];      // 2 nodes x 32
    __shared__ float spart[256];   // 64 rows x 4 wn
    __shared__ float sattn[64];
    __shared__ float scb[128];     // bn + bw
    __shared__ float sWw[128];
    __shared__ float sWl[128];

    const int tid  = threadIdx.x;
    const int w    = tid >> 5, lane = tid & 31;
    const int lg   = lane >> 2, lc = lane & 3;
    const int wm   = w >> 2;     // 0..1
    const int wn   = w & 3;      // 0..3

    if (tid < 128) {
        scb[tid] = bn[tid] + bw[tid];
        sWw[tid] = Ww[tid];
        sWl[tid] = Wl[tid];
    }

    // One-time Wn B-fragment preload (bf16, rn). Physical k quad (ks*16+4lc..+3)
    // -> mma logical k-slots {2lc,2lc+1} (b0) and {2lc+8,2lc+9} (b1).
    // Valid: HW pairs A(m,k_logical) and B(k_logical,n) from threads with the
    // same lc, and both sides use this identical lc-dependent remap; the union
    // over lc covers all 16 physical k exactly once (k-sum is perm-invariant).
    uint32_t breg[8][4][2];
#pragma unroll
    for (int ks = 0; ks < 8; ks++)
#pragma unroll
        for (int ni = 0; ni < 4; ni++) {
            const float4 v = *(const float4*)(Wn + (size_t)(wn * 32 + ni * 8 + lg) * 128
                                              + ks * 16 + 4 * lc);
            breg[ks][ni][0] = pack_bf16(v.x, v.y);
            breg[ks][ni][1] = pack_bf16(v.z, v.w);
        }

    const long rowMax = (long)N * 32 - 1;   // last valid global row of x_nb [N*32, 128]
    const int grid = gridDim.x;

    for (int t = blockIdx.x; t < numTiles; t += grid) {
        __syncthreads();   // protect smem reuse across tiles

        // ---- load tile: 64 rows x 128 fp32 -> bf16 smem ----
        {
            float4 v[8];
            const long r0 = (long)t * 64;
#pragma unroll
            for (int u = 0; u < 8; u++) {
                const int qi = tid + u * 256;
                long gr = r0 + (qi >> 5);
                if (gr > rowMax) gr = rowMax;          // FIX: clamp row index vs row bound
                v[u] = __ldg((const float4*)x_nb + gr * 32 + (qi & 31));
            }
#pragma unroll
            for (int u = 0; u < 8; u++) {
                const int qi = tid + u * 256;
                const int row = qi >> 5, c4 = qi & 31;
                __nv_bfloat162* dst = (__nv_bfloat162*)(sA + row * ATS + c4 * 4);
                dst[0] = __floats2bfloat162_rn(v[u].x, v[u].y);
                dst[1] = __floats2bfloat162_rn(v[u].z, v[u].w);
            }
            if (tid < 64) {
                long node = (long)t * 2 + (tid >> 5); if (node > N - 1) node = N - 1;
                ((float4*)sxs)[tid] = __ldg((const float4*)g_xs + node * 32 + (tid & 31));
            } else if (tid < 80) {
                const int j = tid - 64;
                long wi = (long)t * 16 + j;
                const long wmaxq = (long)N * 8 - 1; if (wi > wmaxq) wi = wmaxq;
                ((float4*)swt)[j] = __ldg((const float4*)weight + wi);
            }
        }
        __syncthreads();

        // ---- GEMM: warp M32 x N32, K=128 (8 k16-slices), B in regs ----
        float acc[2][4][4];
#pragma unroll
        for (int mi = 0; mi < 2; mi++)
#pragma unroll
            for (int ni = 0; ni < 4; ni++)
#pragma unroll
                for (int j = 0; j < 4; j++) acc[mi][ni][j] = 0.f;

#pragma unroll
        for (int ks = 0; ks < 8; ks++) {
            uint32_t a[2][4];
#pragma unroll
            for (int mi = 0; mi < 2; mi++) {
                const int r = wm * 32 + mi * 16 + lg;
                const uint2 q0 = *(const uint2*)(sA + r * ATS + ks * 16 + 4 * lc);
                const uint2 q1 = *(const uint2*)(sA + (r + 8) * ATS + ks * 16 + 4 * lc);
                a[mi][0] = q0.x; a[mi][2] = q0.y;
                a[mi][1] = q1.x; a[mi][3] = q1.y;
            }
#pragma unroll
            for (int ni = 0; ni < 4; ni++) {
                mma_bf16(acc[0][ni], a[0], breg[ks][ni]);
                mma_bf16(acc[1][ni], a[1], breg[ks][ni]);
            }
        }

        // ---- scores: h = n_s + x_s + (bn+bw) + weight*Ww ; leaky(0.1) ; dot Wl ----
#pragma unroll
        for (int mi = 0; mi < 2; mi++)
#pragma unroll
            for (int rh = 0; rh < 2; rh++) {
                const int r = wm * 32 + mi * 16 + rh * 8 + lg;   // 0..63
                const int node = r >> 5, k = r & 31;
                const float wgt = swt[node * 32 + k];
                float p = 0.f;
#pragma unroll
                for (int ni = 0; ni < 4; ni++)
#pragma unroll
                    for (int cc = 0; cc < 2; cc++) {
                        const int d = wn * 32 + ni * 8 + 2 * lc + cc;
                        float h = acc[mi][ni][rh * 2 + cc] + sxs[node * 128 + d]
                                + fmaf(wgt, sWw[d], scb[d]);
                        h = fmaxf(h, 0.f) + 0.1f * fminf(h, 0.f);
                        p = fmaf(sWl[d], h, p);
                    }
                p += __shfl_xor_sync(0xffffffffu, p, 1);
                p += __shfl_xor_sync(0xffffffffu, p, 2);
                if (lc == 0) spart[r * 4 + wn] = p;
            }
        __syncthreads();

        // ---- softmax over K=32 per node (bl dropped: softmax-invariant) ----
        if (w < 2) {
            const int r = w * 32 + lane;    // node = w, k = lane
            float s = spart[r * 4] + spart[r * 4 + 1] + spart[r * 4 + 2] + spart[r * 4 + 3];
            float m = s;
#pragma unroll
            for (int o = 16; o; o >>= 1) m = fmaxf(m, __shfl_xor_sync(0xffffffffu, m, o));
            float e = expf(s - m);
            float su = e;
#pragma unroll
            for (int o = 16; o; o >>= 1) su += __shfl_xor_sync(0xffffffffu, su, o);
            sattn[r] = e / su;
        }
        __syncthreads();

        // ---- output: out[n,d] = sum_k attn[k] * x_nb[n,k,d]  (fp32, L1-hot) ----
        {
            const int node = tid >> 7, d = tid & 127;
            const long gn = (long)t * 2 + node;
            if (gn < N) {
                const float* src = x_nb + (gn * 32) * 128 + d;
                const float* at  = sattn + node * 32;
                float s = 0.f;
#pragma unroll
                for (int k = 0; k < 32; k++)
                    s = fmaf(at[k], __ldg(src + k * 128), s);
                out[gn * 128 + d] = s;
            }
        }
    }
}

// ---------------------------------------------------------------------------
extern "C" void kernel_launch(void* const* d_in, const int* in_sizes, int n_in,
                              void* d_out, int out_size)
{
    const float* x      = (const float*)d_in[0];
    const float* x_nb   = (const float*)d_in[1];
    const float* weight = (const float*)d_in[2];
    const float* Wx     = (const float*)d_in[3];
    const float* bx     = (const float*)d_in[4];
    const float* Wn     = (const float*)d_in[5];
    const float* bn     = (const float*)d_in[6];
    const float* Ww     = (const float*)d_in[7];
    const float* bw     = (const float*)d_in[8];
    const float* Wl     = (const float*)d_in[9];
    // d_in[10] = bl: softmax-invariant, unused.
    float* out = (float*)d_out;

    const int N = in_sizes[0] / 128;

    const size_t smem1 = (size_t)(2 * 128 * STX + 128) * sizeof(float);
    cudaFuncSetAttribute(xs_kernel, cudaFuncAttributeMaxDynamicSharedMemorySize, (int)smem1);

    int nSM = 148;
    cudaDeviceGetAttribute(&nSM, cudaDevAttrMultiProcessorCount, 0);

    const int blocks1 = (N + 127) / 128;
    xs_kernel<<<blocks1, 256, smem1>>>(x, Wx, bx, N);

    const int numTiles = (N + 1) / 2;
    int grid = 2 * nSM;
    if (grid > numTiles) grid = numTiles;
    gnn_main_kernel<<<grid, 256>>>(x_nb, weight, Wn, bn, Ww, bw, Wl, out, N, numTiles);
}